// round 13
// baseline (speedup 1.0000x reference)
#include <cuda_runtime.h>
#include <cuda_fp16.h>
#include <cuda.h>
#include <cstdint>
#include <math.h>

typedef __half fp16;

// ---- arch gate: tcgen05 only exists on arch-specific (sm_103a) targets ----
#if defined(__CUDA_ARCH__) && ( \
      defined(__CUDA_ARCH_FEAT_SM103_ALL) || \
      defined(__CUDA_ARCH_FEAT_SM100_ALL) || \
      (defined(__CUDA_ARCH_SPECIFIC__) && (__CUDA_ARCH_SPECIFIC__ == 1030 || __CUDA_ARCH_SPECIFIC__ == 1000)) )
#define HAS_TC 1
#else
#define HAS_TC 0
#endif

// ---- problem dims ----
#define M_DIM 4096
#define H_DIM 4096
#define I_DIM 11008

// ---- tile config: cg2 pair computes M=256 x N=256, persistent clusters ----
#define BM 128          // per CTA
#define KC 128          // fp16 per K-chunk (two 64-elem SW128 sub-tiles)
#define NTHREADS 256    // w0 MMA (leader), w1 TMA producer, w2-3 wd-convert, w4-7 epilogue
#define NSTAGE 3
#define NCLUSTERS 74

// ---- smem stage layout (bytes): A = two 16KB SW128 sub-tiles, B-half likewise ----
#define OFF_A0 0
#define OFF_A1 (16*1024)
#define OFF_B0 (32*1024)
#define OFF_B1 (48*1024)
#define STAGE_BYTES (64*1024)
#define SMEM_STAGE0 1024
#define SMEM_TOTAL (SMEM_STAGE0 + NSTAGE*STAGE_BYTES)   // 197632 B

// bytes delivered per chunk into the PAIR (leader's barrier sees both CTAs)
#define CHUNK_TX_BYTES (2 * 64 * 1024)

// mbarrier offsets
#define MB_MMA(s)  (8   + (s)*8)    // per-chunk commit (gates producers)
#define MB_LD(s)   (56  + (s)*8)    // loads done (leader: 1 arrive + tx)
#define MB_TILE(b) (104 + (b)*8)    // tile's MMAs complete (gates epilogue)
#define MB_EPI(b)  (120 + (b)*8)    // epilogue done (256 arrives, leader)

// idesc: kind::f16, F32 acc(1<<4), FP16xFP16 (atype=btype=0), N=256, M=256 (pair)
#define MMA_IDESC ((1u<<4)|((256/8)<<17)|((256/16)<<24))

// SW128 K-major smem descriptor base (layout=2, version=1, SBO=64, LBO=1)
#define SMEM_DESC_BASE_SW128 \
    ((uint64_t(2) << 61) | (uint64_t(1) << 46) | (uint64_t(64) << 32) | (uint64_t(1) << 16))

// ---- device scratch (allocation-free rule) ----
__device__ fp16 g_x  [(size_t)M_DIM * H_DIM];
__device__ fp16 g_wgu[(size_t)2 * I_DIM * H_DIM];
__device__ fp16 g_wd [(size_t)H_DIM * I_DIM];
__device__ fp16 g_h  [(size_t)M_DIM * I_DIM];

// ======================= generic PTX helpers =======================

__device__ __forceinline__ uint32_t smem_u32(const void* p) {
    uint32_t a;
    asm("{ .reg .u64 t; cvta.to.shared.u64 t, %1; cvt.u32.u64 %0, t; }" : "=r"(a) : "l"(p));
    return a;
}
__device__ __forceinline__ uint32_t elect_one() {
    uint32_t pred;
    asm volatile("{\n\t.reg .pred p;\n\telect.sync _|p, 0xFFFFFFFF;\n\tselp.b32 %0, 1, 0, p;\n\t}" : "=r"(pred));
    return pred;
}

#define MBARRIER_INIT(mbar, count) \
    asm volatile("mbarrier.init.shared.b64 [%0], %1;" \
        :: "r"((uint32_t)(mbar)), "r"((uint32_t)(count)) : "memory")

#define MBARRIER_ARRIVE_LOCAL(mbar) \
    asm volatile("mbarrier.arrive.release.cta.shared::cta.b64 _, [%0];" \
        :: "r"((uint32_t)(mbar)) : "memory")

#define MBARRIER_ARRIVE_CLUSTER(local_mbar_addr, target_rank) \
    asm volatile( \
        "{\n\t.reg .b32 remAddr32;\n\t" \
        "mapa.shared::cluster.u32 remAddr32, %0, %1;\n\t" \
        "mbarrier.arrive.release.cluster.shared::cluster.b64 _, [remAddr32];\n\t}" \
        :: "r"((uint32_t)(local_mbar_addr)), "r"((uint32_t)(target_rank)) : "memory")

#define MBARRIER_EXPECT_TX(mbar, tx_bytes) \
    asm volatile("mbarrier.arrive.expect_tx.shared.b64 _, [%0], %1;" \
        :: "r"((uint32_t)(mbar)), "r"((uint32_t)(tx_bytes)) : "memory")

#define MBARRIER_WAIT_PARITY(mbar_addr, phase_parity) do { \
    uint32_t _mbar = (uint32_t)(mbar_addr); \
    uint32_t _parity = (uint32_t)(phase_parity); \
    uint32_t _done; \
    asm volatile( \
        "{\n\t.reg .pred p;\n\t" \
        "mbarrier.try_wait.parity.acquire.cta.shared::cta.b64 p, [%1], %2;\n\t" \
        "selp.b32 %0, 1, 0, p;\n\t}" \
        : "=r"(_done) : "r"(_mbar), "r"(_parity) : "memory"); \
    if (!_done) { \
        asm volatile( \
            "{\n\t.reg .pred P1;\n\t" \
            "WAIT_LOOP_%=:\n\t" \
            "mbarrier.try_wait.parity.acquire.cta.shared::cta.b64 P1, [%0], %1, 0x989680;\n\t" \
            "@P1 bra.uni WAIT_DONE_%=;\n\t" \
            "bra.uni WAIT_LOOP_%=;\n\t" \
            "WAIT_DONE_%=:\n\t}" \
            :: "r"(_mbar), "r"(_parity) : "memory"); \
    } \
} while (0)

#define CLUSTER_SYNC() do { \
    asm volatile("barrier.cluster.arrive.aligned;" ::: "memory"); \
    asm volatile("barrier.cluster.wait.aligned;" ::: "memory"); \
} while (0)

__device__ __forceinline__ uint64_t make_desc(uint32_t addr) {
    return SMEM_DESC_BASE_SW128 | ((uint64_t)(addr >> 4) & 0x3FFF);
}

// cg2 TMA load: both CTAs execute; complete_tx targets CTA0's (leader's) barrier
// via Sm100MmaPeerBitMask (clear bit 24 of the local barrier address).
__device__ __forceinline__ void tma_cg2(uint32_t dst, const void* map,
                                        int x, int y, uint32_t mbar) {
    asm volatile(
        "{\n\t"
        ".reg .b32 lb;\n\t"
        "and.b32 lb, %5, 0xFEFFFFFF;\n\t"
        "cp.async.bulk.tensor.3d.cta_group::2.shared::cluster.global"
        ".tile.mbarrier::complete_tx::bytes "
        "[%0], [%1, {%2, %3, %4}], [lb];\n\t"
        "}"
        :: "r"(dst), "l"(map), "r"(x), "r"(y), "r"(0), "r"(mbar)
        : "memory");
}

// ======================= tcgen05 cg2 helpers =======================

__device__ __forceinline__ void mma_ss_cg2(uint32_t d, uint64_t ad, uint64_t bd,
                                           uint32_t idesc, uint32_t en) {
    asm volatile(
        "{\n\t"
        ".reg .pred p;\n\t"
        "setp.ne.u32 p, %4, 0;\n\t"
        "tcgen05.mma.cta_group::2.kind::f16 [%0], %1, %2, %3, {%5, %5, %5, %5, %5, %5, %5, %5}, p;\n\t"
        "}"
        :: "r"(d), "l"(ad), "l"(bd), "r"(idesc), "r"(en), "r"(0u)
        : "memory");
}
__device__ __forceinline__ void tc_alloc_cg2(uint32_t smem_result_addr, uint32_t nCols) {
    asm volatile("tcgen05.alloc.cta_group::2.sync.aligned.shared::cta.b32 [%0], %1;"
        :: "r"(smem_result_addr), "r"(nCols) : "memory");
}
__device__ __forceinline__ void tc_dealloc_cg2(uint32_t tmem_addr, uint32_t nCols) {
    asm volatile("tcgen05.dealloc.cta_group::2.sync.aligned.b32 %0, %1;"
        :: "r"(tmem_addr), "r"(nCols));
}
__device__ __forceinline__ void tc_relinquish_cg2() {
    asm volatile("tcgen05.relinquish_alloc_permit.cta_group::2.sync.aligned;");
}
__device__ __forceinline__ void tc_commit_mc_cg2(uint32_t mbar, uint16_t mask) {
    asm volatile("tcgen05.commit.cta_group::2.mbarrier::arrive::one.shared::cluster.multicast::cluster.b64 [%0], %1;"
        :: "r"(mbar), "h"(mask) : "memory");
}
__device__ __forceinline__ void tc_fence_after() {
    asm volatile("tcgen05.fence::after_thread_sync;" ::: "memory");
}
__device__ __forceinline__ void tc_fence_before() {
    asm volatile("tcgen05.fence::before_thread_sync;" ::: "memory");
}
__device__ __forceinline__ void tc_wait_ld() {
    asm volatile("tcgen05.wait::ld.sync.aligned;" ::: "memory");
}
__device__ __forceinline__ void tc_ld32(uint32_t* r, uint32_t tmem_addr) {
    asm volatile(
        "tcgen05.ld.sync.aligned.32x32b.x32.b32 "
        "{%0, %1, %2, %3, %4, %5, %6, %7, "
        " %8, %9, %10, %11, %12, %13, %14, %15, "
        " %16, %17, %18, %19, %20, %21, %22, %23, "
        " %24, %25, %26, %27, %28, %29, %30, %31}, [%32];"
        : "=r"(r[0]),  "=r"(r[1]),  "=r"(r[2]),  "=r"(r[3]),
          "=r"(r[4]),  "=r"(r[5]),  "=r"(r[6]),  "=r"(r[7]),
          "=r"(r[8]),  "=r"(r[9]),  "=r"(r[10]), "=r"(r[11]),
          "=r"(r[12]), "=r"(r[13]), "=r"(r[14]), "=r"(r[15]),
          "=r"(r[16]), "=r"(r[17]), "=r"(r[18]), "=r"(r[19]),
          "=r"(r[20]), "=r"(r[21]), "=r"(r[22]), "=r"(r[23]),
          "=r"(r[24]), "=r"(r[25]), "=r"(r[26]), "=r"(r[27]),
          "=r"(r[28]), "=r"(r[29]), "=r"(r[30]), "=r"(r[31])
        : "r"(tmem_addr));
}

// ======================= persistent fused GEMM (cg2 + TMA, fp16, KC=128) ==========
// grid (148,1,1), cluster (2,1,1) -> 74 persistent clusters.
// pair q = cid + 74*j ; pmx = q&15 (M pair), nb = q>>4 (N tile).
// MODE 1: gu slice, SwiGLU epilogue -> h fp16 (NPAIRS = 1376, K=4096, nch=32).
//         Warps 2-3 additionally convert wd fp32->fp16 (consumed only by GEMM2).
// MODE 0: out = h @ Wd^T, fp32 epilogue    (NPAIRS = 256, K=11008, nch=86)
template<int MODE>
__global__ void __launch_bounds__(NTHREADS, 1) __cluster_dims__(2, 1, 1)
mlp_gemm(const __grid_constant__ CUtensorMap tma_a,
         const __grid_constant__ CUtensorMap tma_b,
         const fp16* __restrict__ A,
         const fp16* __restrict__ B,
         const fp16* __restrict__ B1,
         int K, int ldout,
         float* __restrict__ Cout,
         fp16* __restrict__ H,
         const float4* __restrict__ wd_src,
         __half2* __restrict__ wd_dst,
         long wd_n4)
{
    extern __shared__ __align__(1024) char smem[];
    const int tid = threadIdx.x;
    const int cid = blockIdx.x >> 1;
    const uint32_t rank = (uint32_t)(blockIdx.x & 1);
    const int NPAIRS = (MODE == 1) ? (16 * 86) : (16 * 16);
    const int nch = K / KC;
    const int ntiles = (NPAIRS - cid + (NCLUSTERS - 1)) / NCLUSTERS;

#if HAS_TC
    const uint32_t sb = smem_u32(smem);
    const int wid = tid >> 5;

    if (wid == 0) tc_alloc_cg2(sb + 0, 512);
    if (tid == 0) {
#pragma unroll
        for (int s = 0; s < NSTAGE; ++s) {
            MBARRIER_INIT(sb + MB_MMA(s), 1);
            MBARRIER_INIT(sb + MB_LD(s), 1);     // 1 arrive (expect_tx) + tx bytes
        }
#pragma unroll
        for (int b = 0; b < 2; ++b) {
            MBARRIER_INIT(sb + MB_TILE(b), 1);
            MBARRIER_INIT(sb + MB_EPI(b), 256);  // 128 local + 128 remote (leader)
        }
    }
    __syncthreads();
    uint32_t tmem;
    asm volatile("ld.shared.b32 %0, [%1];" : "=r"(tmem) : "r"(sb));
    CLUSTER_SYNC();

    if (wid == 1) {
        // ================= TMA producer (single thread per CTA) =================
        if (elect_one()) {
            long g = 0;
            for (int j = 0; j < ntiles; ++j) {
                const int q = cid + NCLUSTERS * j;
                const int pmx = q & 15, nb = q >> 4;
                const int arow = (pmx * 2 + (int)rank) * BM;
                const int brow = (MODE == 1)
                    ? ((int)rank * I_DIM + nb * 128)
                    : (nb * 256 + (int)rank * 128);
                for (int i = 0; i < nch; ++i, ++g) {
                    const int s = (int)(g % NSTAGE);
                    if (g >= NSTAGE)
                        MBARRIER_WAIT_PARITY(sb + MB_MMA(s), (int)((g / NSTAGE - 1) & 1));
                    const uint32_t stage = sb + SMEM_STAGE0 + (uint32_t)s * STAGE_BYTES;
                    if (rank == 0)
                        MBARRIER_EXPECT_TX(sb + MB_LD(s), CHUNK_TX_BYTES);
                    const int k0 = i * KC;
                    tma_cg2(stage + OFF_A0, &tma_a, k0,      arow, sb + MB_LD(s));
                    tma_cg2(stage + OFF_A1, &tma_a, k0 + 64, arow, sb + MB_LD(s));
                    tma_cg2(stage + OFF_B0, &tma_b, k0,      brow, sb + MB_LD(s));
                    tma_cg2(stage + OFF_B1, &tma_b, k0 + 64, brow, sb + MB_LD(s));
                }
            }
        }
    } else if (wid == 0 && rank == 0) {
        // ================= MMA issue warp (leader only) =================
        long g = 0;
        for (int j = 0; j < ntiles; ++j) {
            const int b = j & 1;
            if (j >= 2)
                MBARRIER_WAIT_PARITY(sb + MB_EPI(b), ((j - 2) >> 1) & 1);
            tc_fence_after();                     // order vs epilogue TMEM reads
            const uint32_t dbuf = tmem + (uint32_t)b * 256;
            for (int i = 0; i < nch; ++i, ++g) {
                const int s = (int)(g % NSTAGE);
                MBARRIER_WAIT_PARITY(sb + MB_LD(s), (int)((g / NSTAGE) & 1));
                if (elect_one()) {
                    const uint32_t stage = sb + SMEM_STAGE0 + (uint32_t)s * STAGE_BYTES;
                    uint32_t en = (i != 0) ? 1u : 0u;
#pragma unroll
                    for (int h = 0; h < 2; ++h) {
                        const uint64_t ad = make_desc(stage + OFF_A0 + h * (16*1024));
                        const uint64_t bd = make_desc(stage + OFF_B0 + h * (16*1024));
#pragma unroll
                        for (int kk = 0; kk < 4; ++kk) {
                            mma_ss_cg2(dbuf, ad + kk*2, bd + kk*2, MMA_IDESC, en);
                            en = 1;
                        }
                    }
                    tc_commit_mc_cg2(sb + MB_MMA(s), 0x3);
                    if (i == nch - 1) tc_commit_mc_cg2(sb + MB_TILE(b), 0x3);
                }
            }
        }
    } else if (wid == 2 || wid == 3) {
        // ================= spare warps: wd fp32->fp16 convert (MODE 1 only) ======
        if (MODE == 1) {
            const long stride = (long)(2 * NCLUSTERS) * 64;
            for (long i = (long)blockIdx.x * 64 + (tid - 64); i < wd_n4; i += stride) {
                float4 v = wd_src[i];
                wd_dst[2*i]   = __floats2half2_rn(v.x, v.y);
                wd_dst[2*i+1] = __floats2half2_rn(v.z, v.w);
            }
        }
    } else if (wid >= 4) {
        // ================= epilogue warpgroup (warps 4-7, 128 threads) ===========
        const int et = tid - 128;                 // 0..127 -> D row within CTA
        for (int j = 0; j < ntiles; ++j) {
            const int b = j & 1;
            MBARRIER_WAIT_PARITY(sb + MB_TILE(b), (j >> 1) & 1);
            tc_fence_after();
            const int q = cid + NCLUSTERS * j;
            const int pmx = q & 15, nb = q >> 4;
            const uint32_t tb = tmem + (uint32_t)b * 256;
            const int m = (pmx * 2 + (int)rank) * BM + et;
            if (MODE == 1) {
                fp16* hh = H + (size_t)m * ldout + (size_t)nb * 128;
#pragma unroll
                for (int c0 = 0; c0 < 128; c0 += 32) {
                    uint32_t gr[32], ur[32];
                    tc_ld32(gr, tb + c0);
                    tc_ld32(ur, tb + 128 + c0);
                    tc_wait_ld();
                    uint32_t hp[16];
#pragma unroll
                    for (int jj = 0; jj < 16; ++jj) {
                        float g0 = __uint_as_float(gr[2*jj]);
                        float g1 = __uint_as_float(gr[2*jj+1]);
                        float u0 = __uint_as_float(ur[2*jj]);
                        float u1 = __uint_as_float(ur[2*jj+1]);
                        float h0 = g0 * u0 / (1.0f + __expf(-g0));
                        float h1 = g1 * u1 / (1.0f + __expf(-g1));
                        __half2 hv = __floats2half2_rn(h0, h1);
                        hp[jj] = *reinterpret_cast<uint32_t*>(&hv);
                    }
#pragma unroll
                    for (int v = 0; v < 4; ++v) {
                        uint4 vh = make_uint4(hp[4*v], hp[4*v+1], hp[4*v+2], hp[4*v+3]);
                        *reinterpret_cast<uint4*>(hh + c0 + v * 8) = vh;
                    }
                }
            } else {
                float* co = Cout + (size_t)m * ldout + (size_t)nb * 256;
#pragma unroll
                for (int c0 = 0; c0 < 256; c0 += 32) {
                    uint32_t dr[32];
                    tc_ld32(dr, tb + c0);
                    tc_wait_ld();
#pragma unroll
                    for (int v = 0; v < 8; ++v) {
                        float4 f = make_float4(__uint_as_float(dr[4*v]),
                                               __uint_as_float(dr[4*v+1]),
                                               __uint_as_float(dr[4*v+2]),
                                               __uint_as_float(dr[4*v+3]));
                        *reinterpret_cast<float4*>(co + c0 + v * 4) = f;
                    }
                }
            }
            tc_fence_before();
            if (rank == 0) { MBARRIER_ARRIVE_LOCAL(sb + MB_EPI(b)); }
            else           { MBARRIER_ARRIVE_CLUSTER(sb + MB_EPI(b), 0); }
        }
    }
    __syncthreads();
    CLUSTER_SYNC();
    if (wid == 0) {
        tc_relinquish_cg2();
        tc_dealloc_cg2(tmem, 512);
    }
    CLUSTER_SYNC();

#else
    // ---------------- SIMT fallback (plain sm_103 target; never the picked cubin) ----
    if (MODE == 1) {
        const long stride = (long)(2 * NCLUSTERS) * NTHREADS;
        for (long i = (long)blockIdx.x * NTHREADS + tid; i < wd_n4; i += stride) {
            float4 v = wd_src[i];
            wd_dst[2*i]   = __floats2half2_rn(v.x, v.y);
            wd_dst[2*i+1] = __floats2half2_rn(v.z, v.w);
        }
        __syncthreads();
    }

    float* fA  = reinterpret_cast<float*>(smem);          // [8][128]
    float* fB0 = fA  + 8 * 128;
    float* fB1 = fB0 + 8 * 128;
    const int tx = tid & 15;
    const int ty = (tid >> 4) & 15;
    const int lr = (tid & 255) >> 1;
    const int lc = (tid & 1) << 2;

    for (int j = 0; j < ntiles; ++j) {
        const int q = cid + NCLUSTERS * j;
        const int pmx = q & 15, nb = q >> 4;
        const int mbx = pmx * 2 + (int)rank;
        const fp16* a = A + (size_t)mbx * BM * K;
        const fp16* b0 = (MODE == 1)
            ? ((rank ? B1 : B) + (size_t)nb * 128 * K)
            : (B + (size_t)nb * 256 * K);
        const fp16* b1 = (MODE == 1) ? b0 : (B + ((size_t)nb * 256 + 128) * K);

        float acc0[8][8], acc1[8][8];
#pragma unroll
        for (int i = 0; i < 8; i++)
#pragma unroll
            for (int jj = 0; jj < 8; jj++) { acc0[i][jj] = 0.0f; acc1[i][jj] = 0.0f; }

        for (int k0 = 0; k0 < K; k0 += 8) {
            __syncthreads();
            if (tid < 256) {
#pragma unroll
                for (int c = 0; c < 4; ++c) {
                    int k = k0 + lc + c;
                    size_t off = (size_t)lr * K + k;
                    fA [(lc + c) * 128 + lr] = __half2float(a[off]);
                    fB0[(lc + c) * 128 + lr] = __half2float(b0[off]);
                    fB1[(lc + c) * 128 + lr] = __half2float(b1[off]);
                }
            }
            __syncthreads();
            if (tid < 256) {
#pragma unroll
                for (int k = 0; k < 8; k++) {
                    float ra[8], rb0[8], rb1[8];
#pragma unroll
                    for (int i = 0; i < 8; i++) ra[i]  = fA [k * 128 + ty * 8 + i];
#pragma unroll
                    for (int jj = 0; jj < 8; jj++) { rb0[jj] = fB0[k * 128 + tx * 8 + jj]; rb1[jj] = fB1[k * 128 + tx * 8 + jj]; }
#pragma unroll
                    for (int i = 0; i < 8; i++)
#pragma unroll
                        for (int jj = 0; jj < 8; jj++) {
                            acc0[i][jj] = fmaf(ra[i], rb0[jj], acc0[i][jj]);
                            acc1[i][jj] = fmaf(ra[i], rb1[jj], acc1[i][jj]);
                        }
                }
            }
        }
        if (tid < 256) {
            if (MODE == 1) {
#pragma unroll
                for (int i = 0; i < 8; i++) {
                    int m = mbx * BM + ty * 8 + i;
                    fp16* hh = H + (size_t)m * ldout + (size_t)nb * 128 + tx * 8;
#pragma unroll
                    for (int jj = 0; jj < 8; jj++) {
                        float g = acc0[i][jj], u = acc1[i][jj];
                        float h = g * u / (1.0f + __expf(-g));
                        hh[jj] = __float2half(h);
                    }
                }
            } else {
#pragma unroll
                for (int i = 0; i < 8; i++) {
                    int m = mbx * BM + ty * 8 + i;
                    float* co = Cout + (size_t)m * ldout + (size_t)nb * 256 + tx * 8;
#pragma unroll
                    for (int jj = 0; jj < 8; jj++) { co[jj] = acc0[i][jj]; co[128 + jj] = acc1[i][jj]; }
                }
            }
        }
        __syncthreads();
    }
#endif
}

// ======================= fp32 -> fp16 convert =======================
__global__ void convert_kernel(const float4* __restrict__ src,
                               __half2* __restrict__ dst, long n4)
{
    long i = (long)blockIdx.x * blockDim.x + threadIdx.x;
    if (i >= n4) return;
    float4 v = src[i];
    dst[2*i]   = __floats2half2_rn(v.x, v.y);
    dst[2*i+1] = __floats2half2_rn(v.z, v.w);
}

// ======================= host: tensormap building =======================

typedef CUresult (*EncodeTiledFn)(
    CUtensorMap*, CUtensorMapDataType, cuuint32_t, void*,
    const cuuint64_t*, const cuuint64_t*, const cuuint32_t*, const cuuint32_t*,
    CUtensorMapInterleave, CUtensorMapSwizzle, CUtensorMapL2promotion,
    CUtensorMapFloatOOBfill);

static void build_map(EncodeTiledFn enc, CUtensorMap* m, void* base,
                      unsigned long long dim0, unsigned long long dim1)
{
    cuuint64_t dims[3]    = {dim0, dim1, 1};
    cuuint64_t strides[2] = {dim0 * 2ull, dim0 * dim1 * 2ull};
    cuuint32_t box[3]     = {64, BM, 1};          // 64 fp16 = 128B (SW128 atom), 128 rows
    cuuint32_t es[3]      = {1, 1, 1};
    enc(m, CU_TENSOR_MAP_DATA_TYPE_FLOAT16, 3, base, dims, strides, box, es,
        CU_TENSOR_MAP_INTERLEAVE_NONE, CU_TENSOR_MAP_SWIZZLE_128B,
        CU_TENSOR_MAP_L2_PROMOTION_L2_128B, CU_TENSOR_MAP_FLOAT_OOB_FILL_NONE);
}

// ======================= launch =======================
extern "C" void kernel_launch(void* const* d_in, const int* in_sizes, int n_in,
                              void* d_out, int out_size)
{
    const float* x   = (const float*)d_in[0];
    const float* wgu = (const float*)d_in[1];
    const float* wd  = (const float*)d_in[2];
    float* out       = (float*)d_out;

    fp16 *xc, *wguc, *wdc, *hc;
    cudaGetSymbolAddress((void**)&xc,  g_x);
    cudaGetSymbolAddress((void**)&wguc, g_wgu);
    cudaGetSymbolAddress((void**)&wdc, g_wd);
    cudaGetSymbolAddress((void**)&hc,  g_h);

    // driver entry point for tensormap encoding (avoids -lcuda link dependency)
    void* fn = nullptr;
    cudaDriverEntryPointQueryResult qr;
    cudaGetDriverEntryPoint("cuTensorMapEncodeTiled", &fn, cudaEnableDefault, &qr);
    EncodeTiledFn enc = (EncodeTiledFn)fn;

    CUtensorMap map_x, map_wgu, map_h, map_wd;
    build_map(enc, &map_x,   xc,   H_DIM, M_DIM);          // [4096, 4096]
    build_map(enc, &map_wgu, wguc, H_DIM, 2ull * I_DIM);   // [4096, 22016]
    build_map(enc, &map_h,   hc,   I_DIM, M_DIM);          // [11008, 4096]
    build_map(enc, &map_wd,  wdc,  I_DIM, H_DIM);          // [11008, 4096]

    cudaFuncSetAttribute(mlp_gemm<0>, cudaFuncAttributeMaxDynamicSharedMemorySize, SMEM_TOTAL);
    cudaFuncSetAttribute(mlp_gemm<1>, cudaFuncAttributeMaxDynamicSharedMemorySize, SMEM_TOTAL);

    // convert x + wgu to fp16 up-front (needed by GEMM1). wd is converted
    // INSIDE GEMM1 by its spare warps (overlapped with the mainloop).
    {
        long n4 = (long)M_DIM * H_DIM / 4;
        convert_kernel<<<(unsigned)((n4 + 255) / 256), 256>>>(
            (const float4*)x, (__half2*)xc, n4);
    }
    {
        long n4 = (long)2 * I_DIM * H_DIM / 4;
        convert_kernel<<<(unsigned)((n4 + 255) / 256), 256>>>(
            (const float4*)wgu, (__half2*)wguc, n4);
    }

    const long wd_n4 = (long)H_DIM * I_DIM / 4;

    // GEMM1 (fused SwiGLU -> h fp16, + wd convert on spare warps)
    mlp_gemm<1><<<dim3(2 * NCLUSTERS, 1, 1), NTHREADS, SMEM_TOTAL>>>(
        map_x, map_wgu,
        xc, wguc, wguc + (size_t)I_DIM * H_DIM,
        H_DIM, I_DIM,
        nullptr, hc,
        (const float4*)wd, (__half2*)wdc, wd_n4);

    // GEMM2: out = h @ Wd^T
    mlp_gemm<0><<<dim3(2 * NCLUSTERS, 1, 1), NTHREADS, SMEM_TOTAL>>>(
        map_h, map_wd,
        hc, wdc, nullptr,
        I_DIM, H_DIM,
        out, nullptr,
        nullptr, nullptr, 0);
}

// round 14
// speedup vs baseline: 1.0474x; 1.0474x over previous
#include <cuda_runtime.h>
#include <cuda_fp16.h>
#include <cuda.h>
#include <cstdint>
#include <math.h>

typedef __half fp16;

// ---- arch gate: tcgen05 only exists on arch-specific (sm_103a) targets ----
#if defined(__CUDA_ARCH__) && ( \
      defined(__CUDA_ARCH_FEAT_SM103_ALL) || \
      defined(__CUDA_ARCH_FEAT_SM100_ALL) || \
      (defined(__CUDA_ARCH_SPECIFIC__) && (__CUDA_ARCH_SPECIFIC__ == 1030 || __CUDA_ARCH_SPECIFIC__ == 1000)) )
#define HAS_TC 1
#else
#define HAS_TC 0
#endif

// ---- problem dims ----
#define M_DIM 4096
#define H_DIM 4096
#define I_DIM 11008

// ---- tile config: cg2 pair computes M=256 x N=256, persistent clusters ----
#define BM 128          // per CTA
#define KC 64           // fp16 per K-chunk -> 128B rows (SW128 atom)
#define NTHREADS 256    // w0 MMA (leader), w1 TMA producer, w2-3 wd-convert, w4-7 epilogue
#define NSTAGE 6
#define NCLUSTERS 74

// ---- smem stage layout (bytes): A [128x64 fp16], B-half [128x64 fp16] ----
#define OFF_A 0
#define OFF_B (16*1024)
#define STAGE_BYTES (32*1024)
#define SMEM_STAGE0 1024
#define SMEM_TOTAL (SMEM_STAGE0 + NSTAGE*STAGE_BYTES)   // 197632 B

// bytes delivered per chunk into the PAIR (leader's barrier sees both CTAs)
#define CHUNK_TX_BYTES (4 * 16 * 1024)

// mbarrier offsets
#define MB_MMA(s)  (8   + (s)*8)    // 8..48   : per-chunk commit (gates producers)
#define MB_LD(s)   (56  + (s)*8)    // 56..96  : loads done (leader: 1 arrive + tx)
#define MB_TILE(b) (104 + (b)*8)    // 104,112 : tile's MMAs complete (gates epilogue)
#define MB_EPI(b)  (120 + (b)*8)    // 120,128 : epilogue done (256 arrives, leader)

// idesc: kind::f16, F32 acc(1<<4), FP16xFP16 (atype=btype=0), N=256, M=256 (pair)
#define MMA_IDESC ((1u<<4)|((256/8)<<17)|((256/16)<<24))

// SW128 K-major smem descriptor base (layout=2, version=1, SBO=64, LBO=1)
#define SMEM_DESC_BASE_SW128 \
    ((uint64_t(2) << 61) | (uint64_t(1) << 46) | (uint64_t(64) << 32) | (uint64_t(1) << 16))

// ---- device scratch (allocation-free rule) ----
__device__ fp16 g_x  [(size_t)M_DIM * H_DIM];
__device__ fp16 g_wgu[(size_t)2 * I_DIM * H_DIM];
__device__ fp16 g_wd [(size_t)H_DIM * I_DIM];
__device__ fp16 g_h  [(size_t)M_DIM * I_DIM];

// ======================= generic PTX helpers =======================

__device__ __forceinline__ uint32_t smem_u32(const void* p) {
    uint32_t a;
    asm("{ .reg .u64 t; cvta.to.shared.u64 t, %1; cvt.u32.u64 %0, t; }" : "=r"(a) : "l"(p));
    return a;
}
__device__ __forceinline__ uint32_t elect_one() {
    uint32_t pred;
    asm volatile("{\n\t.reg .pred p;\n\telect.sync _|p, 0xFFFFFFFF;\n\tselp.b32 %0, 1, 0, p;\n\t}" : "=r"(pred));
    return pred;
}

#define MBARRIER_INIT(mbar, count) \
    asm volatile("mbarrier.init.shared.b64 [%0], %1;" \
        :: "r"((uint32_t)(mbar)), "r"((uint32_t)(count)) : "memory")

#define MBARRIER_ARRIVE_LOCAL(mbar) \
    asm volatile("mbarrier.arrive.release.cta.shared::cta.b64 _, [%0];" \
        :: "r"((uint32_t)(mbar)) : "memory")

#define MBARRIER_ARRIVE_CLUSTER(local_mbar_addr, target_rank) \
    asm volatile( \
        "{\n\t.reg .b32 remAddr32;\n\t" \
        "mapa.shared::cluster.u32 remAddr32, %0, %1;\n\t" \
        "mbarrier.arrive.release.cluster.shared::cluster.b64 _, [remAddr32];\n\t}" \
        :: "r"((uint32_t)(local_mbar_addr)), "r"((uint32_t)(target_rank)) : "memory")

#define MBARRIER_EXPECT_TX(mbar, tx_bytes) \
    asm volatile("mbarrier.arrive.expect_tx.shared.b64 _, [%0], %1;" \
        :: "r"((uint32_t)(mbar)), "r"((uint32_t)(tx_bytes)) : "memory")

// acquire wait: required when post-wait code performs generic smem/TMEM-read ordering
#define MBARRIER_WAIT_PARITY(mbar_addr, phase_parity) do { \
    uint32_t _mbar = (uint32_t)(mbar_addr); \
    uint32_t _parity = (uint32_t)(phase_parity); \
    uint32_t _done; \
    asm volatile( \
        "{\n\t.reg .pred p;\n\t" \
        "mbarrier.try_wait.parity.acquire.cta.shared::cta.b64 p, [%1], %2;\n\t" \
        "selp.b32 %0, 1, 0, p;\n\t}" \
        : "=r"(_done) : "r"(_mbar), "r"(_parity) : "memory"); \
    if (!_done) { \
        asm volatile( \
            "{\n\t.reg .pred P1;\n\t" \
            "WAIT_LOOP_%=:\n\t" \
            "mbarrier.try_wait.parity.acquire.cta.shared::cta.b64 P1, [%0], %1, 0x989680;\n\t" \
            "@P1 bra.uni WAIT_DONE_%=;\n\t" \
            "bra.uni WAIT_LOOP_%=;\n\t" \
            "WAIT_DONE_%=:\n\t}" \
            :: "r"(_mbar), "r"(_parity) : "memory"); \
    } \
} while (0)

// relaxed wait: ONLY for waits whose post-wait SMEM accesses are all async-proxy
// (TMA / tcgen05) — producer waits and the leader's load-ready wait qualify.
#define MBARRIER_WAIT_PARITY_RELAXED(mbar_addr, phase_parity) do { \
    uint32_t _mbar = (uint32_t)(mbar_addr); \
    uint32_t _parity = (uint32_t)(phase_parity); \
    uint32_t _done; \
    asm volatile( \
        "{\n\t.reg .pred p;\n\t" \
        "mbarrier.try_wait.parity.relaxed.cta.shared::cta.b64 p, [%1], %2, 0x989680;\n\t" \
        "selp.b32 %0, 1, 0, p;\n\t}" \
        : "=r"(_done) : "r"(_mbar), "r"(_parity) : "memory"); \
    if (!_done) { \
        asm volatile( \
            "{\n\t.reg .pred P1;\n\t" \
            "WAIT_LOOP_%=:\n\t" \
            "mbarrier.try_wait.parity.relaxed.cta.shared::cta.b64 P1, [%0], %1, 0x989680;\n\t" \
            "@P1 bra.uni WAIT_DONE_%=;\n\t" \
            "bra.uni WAIT_LOOP_%=;\n\t" \
            "WAIT_DONE_%=:\n\t}" \
            :: "r"(_mbar), "r"(_parity) : "memory"); \
    } \
} while (0)

#define CLUSTER_SYNC() do { \
    asm volatile("barrier.cluster.arrive.aligned;" ::: "memory"); \
    asm volatile("barrier.cluster.wait.aligned;" ::: "memory"); \
} while (0)

__device__ __forceinline__ uint64_t make_desc(uint32_t addr) {
    return SMEM_DESC_BASE_SW128 | ((uint64_t)(addr >> 4) & 0x3FFF);
}

// cg2 TMA load: both CTAs execute; complete_tx targets CTA0's (leader's) barrier
// via Sm100MmaPeerBitMask (clear bit 24 of the local barrier address).
__device__ __forceinline__ void tma_cg2(uint32_t dst, const void* map,
                                        int x, int y, uint32_t mbar) {
    asm volatile(
        "{\n\t"
        ".reg .b32 lb;\n\t"
        "and.b32 lb, %5, 0xFEFFFFFF;\n\t"
        "cp.async.bulk.tensor.3d.cta_group::2.shared::cluster.global"
        ".tile.mbarrier::complete_tx::bytes "
        "[%0], [%1, {%2, %3, %4}], [lb];\n\t"
        "}"
        :: "r"(dst), "l"(map), "r"(x), "r"(y), "r"(0), "r"(mbar)
        : "memory");
}

// ======================= tcgen05 cg2 helpers =======================

__device__ __forceinline__ void mma_ss_cg2(uint32_t d, uint64_t ad, uint64_t bd,
                                           uint32_t idesc, uint32_t en) {
    asm volatile(
        "{\n\t"
        ".reg .pred p;\n\t"
        "setp.ne.u32 p, %4, 0;\n\t"
        "tcgen05.mma.cta_group::2.kind::f16 [%0], %1, %2, %3, {%5, %5, %5, %5, %5, %5, %5, %5}, p;\n\t"
        "}"
        :: "r"(d), "l"(ad), "l"(bd), "r"(idesc), "r"(en), "r"(0u)
        : "memory");
}
__device__ __forceinline__ void tc_alloc_cg2(uint32_t smem_result_addr, uint32_t nCols) {
    asm volatile("tcgen05.alloc.cta_group::2.sync.aligned.shared::cta.b32 [%0], %1;"
        :: "r"(smem_result_addr), "r"(nCols) : "memory");
}
__device__ __forceinline__ void tc_dealloc_cg2(uint32_t tmem_addr, uint32_t nCols) {
    asm volatile("tcgen05.dealloc.cta_group::2.sync.aligned.b32 %0, %1;"
        :: "r"(tmem_addr), "r"(nCols));
}
__device__ __forceinline__ void tc_relinquish_cg2() {
    asm volatile("tcgen05.relinquish_alloc_permit.cta_group::2.sync.aligned;");
}
__device__ __forceinline__ void tc_commit_mc_cg2(uint32_t mbar, uint16_t mask) {
    asm volatile("tcgen05.commit.cta_group::2.mbarrier::arrive::one.shared::cluster.multicast::cluster.b64 [%0], %1;"
        :: "r"(mbar), "h"(mask) : "memory");
}
__device__ __forceinline__ void tc_fence_after() {
    asm volatile("tcgen05.fence::after_thread_sync;" ::: "memory");
}
__device__ __forceinline__ void tc_fence_before() {
    asm volatile("tcgen05.fence::before_thread_sync;" ::: "memory");
}
__device__ __forceinline__ void tc_wait_ld() {
    asm volatile("tcgen05.wait::ld.sync.aligned;" ::: "memory");
}
__device__ __forceinline__ void tc_ld32(uint32_t* r, uint32_t tmem_addr) {
    asm volatile(
        "tcgen05.ld.sync.aligned.32x32b.x32.b32 "
        "{%0, %1, %2, %3, %4, %5, %6, %7, "
        " %8, %9, %10, %11, %12, %13, %14, %15, "
        " %16, %17, %18, %19, %20, %21, %22, %23, "
        " %24, %25, %26, %27, %28, %29, %30, %31}, [%32];"
        : "=r"(r[0]),  "=r"(r[1]),  "=r"(r[2]),  "=r"(r[3]),
          "=r"(r[4]),  "=r"(r[5]),  "=r"(r[6]),  "=r"(r[7]),
          "=r"(r[8]),  "=r"(r[9]),  "=r"(r[10]), "=r"(r[11]),
          "=r"(r[12]), "=r"(r[13]), "=r"(r[14]), "=r"(r[15]),
          "=r"(r[16]), "=r"(r[17]), "=r"(r[18]), "=r"(r[19]),
          "=r"(r[20]), "=r"(r[21]), "=r"(r[22]), "=r"(r[23]),
          "=r"(r[24]), "=r"(r[25]), "=r"(r[26]), "=r"(r[27]),
          "=r"(r[28]), "=r"(r[29]), "=r"(r[30]), "=r"(r[31])
        : "r"(tmem_addr));
}

// ======================= persistent fused GEMM (cg2 + TMA, fp16) ==================
// grid (148,1,1), cluster (2,1,1) -> 74 persistent clusters.
// pair q = cid + 74*j ; pmx = q&15 (M pair), nb = q>>4 (N tile).
// MODE 1: gu slice, SwiGLU epilogue -> h fp16 (NPAIRS = 1376, K=4096).
//         Warps 2-3 additionally convert wd fp32->fp16 (consumed only by GEMM2,
//         which is stream-ordered after this kernel) using otherwise-idle lanes.
// MODE 0: out = h @ Wd^T, fp32 epilogue    (NPAIRS = 256, K=11008)
template<int MODE>
__global__ void __launch_bounds__(NTHREADS, 1) __cluster_dims__(2, 1, 1)
mlp_gemm(const __grid_constant__ CUtensorMap tma_a,
         const __grid_constant__ CUtensorMap tma_b,
         const fp16* __restrict__ A,
         const fp16* __restrict__ B,
         const fp16* __restrict__ B1,
         int K, int ldout,
         float* __restrict__ Cout,
         fp16* __restrict__ H,
         const float4* __restrict__ wd_src,
         __half2* __restrict__ wd_dst,
         long wd_n4)
{
    extern __shared__ __align__(1024) char smem[];
    const int tid = threadIdx.x;
    const int cid = blockIdx.x >> 1;
    const uint32_t rank = (uint32_t)(blockIdx.x & 1);
    const int NPAIRS = (MODE == 1) ? (16 * 86) : (16 * 16);
    const int nch = K / KC;
    const int ntiles = (NPAIRS - cid + (NCLUSTERS - 1)) / NCLUSTERS;

#if HAS_TC
    const uint32_t sb = smem_u32(smem);
    const int wid = tid >> 5;

    if (wid == 0) tc_alloc_cg2(sb + 0, 512);
    if (tid == 0) {
#pragma unroll
        for (int s = 0; s < NSTAGE; ++s) {
            MBARRIER_INIT(sb + MB_MMA(s), 1);
            MBARRIER_INIT(sb + MB_LD(s), 1);     // 1 arrive (expect_tx) + tx bytes
        }
#pragma unroll
        for (int b = 0; b < 2; ++b) {
            MBARRIER_INIT(sb + MB_TILE(b), 1);
            MBARRIER_INIT(sb + MB_EPI(b), 256);  // 128 local + 128 remote (leader)
        }
    }
    __syncthreads();
    uint32_t tmem;
    asm volatile("ld.shared.b32 %0, [%1];" : "=r"(tmem) : "r"(sb));
    CLUSTER_SYNC();

    if (wid == 1) {
        // ================= TMA producer (single thread per CTA) =================
        if (elect_one()) {
            long g = 0;
            for (int j = 0; j < ntiles; ++j) {
                const int q = cid + NCLUSTERS * j;
                const int pmx = q & 15, nb = q >> 4;
                const int arow = (pmx * 2 + (int)rank) * BM;
                const int brow = (MODE == 1)
                    ? ((int)rank * I_DIM + nb * 128)
                    : (nb * 256 + (int)rank * 128);
                for (int i = 0; i < nch; ++i, ++g) {
                    const int s = (int)(g % NSTAGE);
                    if (g >= NSTAGE)
                        MBARRIER_WAIT_PARITY_RELAXED(sb + MB_MMA(s), (int)((g / NSTAGE - 1) & 1));
                    const uint32_t stage = sb + SMEM_STAGE0 + (uint32_t)s * STAGE_BYTES;
                    if (rank == 0)
                        MBARRIER_EXPECT_TX(sb + MB_LD(s), CHUNK_TX_BYTES);
                    tma_cg2(stage + OFF_A, &tma_a, i * KC, arow, sb + MB_LD(s));
                    tma_cg2(stage + OFF_B, &tma_b, i * KC, brow, sb + MB_LD(s));
                }
            }
        }
    } else if (wid == 0 && rank == 0) {
        // ================= MMA issue warp (leader only) =================
        long g = 0;
        for (int j = 0; j < ntiles; ++j) {
            const int b = j & 1;
            if (j >= 2)
                MBARRIER_WAIT_PARITY(sb + MB_EPI(b), ((j - 2) >> 1) & 1);
            tc_fence_after();                     // order vs epilogue TMEM reads
            const uint32_t dbuf = tmem + (uint32_t)b * 256;
            for (int i = 0; i < nch; ++i, ++g) {
                const int s = (int)(g % NSTAGE);
                MBARRIER_WAIT_PARITY_RELAXED(sb + MB_LD(s), (int)((g / NSTAGE) & 1));
                if (elect_one()) {
                    const uint32_t stage = sb + SMEM_STAGE0 + (uint32_t)s * STAGE_BYTES;
                    const uint64_t ad = make_desc(stage + OFF_A);
                    const uint64_t bd = make_desc(stage + OFF_B);
                    uint32_t en = (i != 0) ? 1u : 0u;
#pragma unroll
                    for (int kk = 0; kk < 4; ++kk) {
                        mma_ss_cg2(dbuf, ad + kk*2, bd + kk*2, MMA_IDESC, en);
                        en = 1;
                    }
                    tc_commit_mc_cg2(sb + MB_MMA(s), 0x3);
                    if (i == nch - 1) tc_commit_mc_cg2(sb + MB_TILE(b), 0x3);
                }
            }
        }
    } else if (wid == 2 || wid == 3) {
        // ================= spare warps: wd fp32->fp16 convert (MODE 1 only) ======
        // Consumed only by GEMM2, which is stream-ordered after this kernel.
        if (MODE == 1) {
            const long stride = (long)(2 * NCLUSTERS) * 64;
            for (long i = (long)blockIdx.x * 64 + (tid - 64); i < wd_n4; i += stride) {
                float4 v = wd_src[i];
                wd_dst[2*i]   = __floats2half2_rn(v.x, v.y);
                wd_dst[2*i+1] = __floats2half2_rn(v.z, v.w);
            }
        }
    } else if (wid >= 4) {
        // ================= epilogue warpgroup (warps 4-7, 128 threads) ===========
        const int et = tid - 128;                 // 0..127 -> D row within CTA
        for (int j = 0; j < ntiles; ++j) {
            const int b = j & 1;
            MBARRIER_WAIT_PARITY(sb + MB_TILE(b), (j >> 1) & 1);
            tc_fence_after();
            const int q = cid + NCLUSTERS * j;
            const int pmx = q & 15, nb = q >> 4;
            const uint32_t tb = tmem + (uint32_t)b * 256;
            const int m = (pmx * 2 + (int)rank) * BM + et;
            if (MODE == 1) {
                fp16* hh = H + (size_t)m * ldout + (size_t)nb * 128;
#pragma unroll
                for (int c0 = 0; c0 < 128; c0 += 32) {
                    uint32_t gr[32], ur[32];
                    tc_ld32(gr, tb + c0);
                    tc_ld32(ur, tb + 128 + c0);
                    tc_wait_ld();
                    uint32_t hp[16];
#pragma unroll
                    for (int jj = 0; jj < 16; ++jj) {
                        float g0 = __uint_as_float(gr[2*jj]);
                        float g1 = __uint_as_float(gr[2*jj+1]);
                        float u0 = __uint_as_float(ur[2*jj]);
                        float u1 = __uint_as_float(ur[2*jj+1]);
                        float h0 = g0 * u0 / (1.0f + __expf(-g0));
                        float h1 = g1 * u1 / (1.0f + __expf(-g1));
                        __half2 hv = __floats2half2_rn(h0, h1);
                        hp[jj] = *reinterpret_cast<uint32_t*>(&hv);
                    }
#pragma unroll
                    for (int v = 0; v < 4; ++v) {
                        uint4 vh = make_uint4(hp[4*v], hp[4*v+1], hp[4*v+2], hp[4*v+3]);
                        *reinterpret_cast<uint4*>(hh + c0 + v * 8) = vh;
                    }
                }
            } else {
                float* co = Cout + (size_t)m * ldout + (size_t)nb * 256;
#pragma unroll
                for (int c0 = 0; c0 < 256; c0 += 32) {
                    uint32_t dr[32];
                    tc_ld32(dr, tb + c0);
                    tc_wait_ld();
#pragma unroll
                    for (int v = 0; v < 8; ++v) {
                        float4 f = make_float4(__uint_as_float(dr[4*v]),
                                               __uint_as_float(dr[4*v+1]),
                                               __uint_as_float(dr[4*v+2]),
                                               __uint_as_float(dr[4*v+3]));
                        *reinterpret_cast<float4*>(co + c0 + v * 4) = f;
                    }
                }
            }
            tc_fence_before();
            if (rank == 0) { MBARRIER_ARRIVE_LOCAL(sb + MB_EPI(b)); }
            else           { MBARRIER_ARRIVE_CLUSTER(sb + MB_EPI(b), 0); }
        }
    }
    __syncthreads();
    CLUSTER_SYNC();
    if (wid == 0) {
        tc_relinquish_cg2();
        tc_dealloc_cg2(tmem, 512);
    }
    CLUSTER_SYNC();

#else
    // ---------------- SIMT fallback (plain sm_103 target; never the picked cubin) ----
    if (MODE == 1) {
        const long stride = (long)(2 * NCLUSTERS) * NTHREADS;
        for (long i = (long)blockIdx.x * NTHREADS + tid; i < wd_n4; i += stride) {
            float4 v = wd_src[i];
            wd_dst[2*i]   = __floats2half2_rn(v.x, v.y);
            wd_dst[2*i+1] = __floats2half2_rn(v.z, v.w);
        }
        __syncthreads();
    }

    float* fA  = reinterpret_cast<float*>(smem);          // [8][128]
    float* fB0 = fA  + 8 * 128;
    float* fB1 = fB0 + 8 * 128;
    const int tx = tid & 15;
    const int ty = (tid >> 4) & 15;
    const int lr = (tid & 255) >> 1;
    const int lc = (tid & 1) << 2;

    for (int j = 0; j < ntiles; ++j) {
        const int q = cid + NCLUSTERS * j;
        const int pmx = q & 15, nb = q >> 4;
        const int mbx = pmx * 2 + (int)rank;
        const fp16* a = A + (size_t)mbx * BM * K;
        const fp16* b0 = (MODE == 1)
            ? ((rank ? B1 : B) + (size_t)nb * 128 * K)
            : (B + (size_t)nb * 256 * K);
        const fp16* b1 = (MODE == 1) ? b0 : (B + ((size_t)nb * 256 + 128) * K);

        float acc0[8][8], acc1[8][8];
#pragma unroll
        for (int i = 0; i < 8; i++)
#pragma unroll
            for (int jj = 0; jj < 8; jj++) { acc0[i][jj] = 0.0f; acc1[i][jj] = 0.0f; }

        for (int k0 = 0; k0 < K; k0 += 8) {
            __syncthreads();
            if (tid < 256) {
#pragma unroll
                for (int c = 0; c < 4; ++c) {
                    int k = k0 + lc + c;
                    size_t off = (size_t)lr * K + k;
                    fA [(lc + c) * 128 + lr] = __half2float(a[off]);
                    fB0[(lc + c) * 128 + lr] = __half2float(b0[off]);
                    fB1[(lc + c) * 128 + lr] = __half2float(b1[off]);
                }
            }
            __syncthreads();
            if (tid < 256) {
#pragma unroll
                for (int k = 0; k < 8; k++) {
                    float ra[8], rb0[8], rb1[8];
#pragma unroll
                    for (int i = 0; i < 8; i++) ra[i]  = fA [k * 128 + ty * 8 + i];
#pragma unroll
                    for (int jj = 0; jj < 8; jj++) { rb0[jj] = fB0[k * 128 + tx * 8 + jj]; rb1[jj] = fB1[k * 128 + tx * 8 + jj]; }
#pragma unroll
                    for (int i = 0; i < 8; i++)
#pragma unroll
                        for (int jj = 0; jj < 8; jj++) {
                            acc0[i][jj] = fmaf(ra[i], rb0[jj], acc0[i][jj]);
                            acc1[i][jj] = fmaf(ra[i], rb1[jj], acc1[i][jj]);
                        }
                }
            }
        }
        if (tid < 256) {
            if (MODE == 1) {
#pragma unroll
                for (int i = 0; i < 8; i++) {
                    int m = mbx * BM + ty * 8 + i;
                    fp16* hh = H + (size_t)m * ldout + (size_t)nb * 128 + tx * 8;
#pragma unroll
                    for (int jj = 0; jj < 8; jj++) {
                        float g = acc0[i][jj], u = acc1[i][jj];
                        float h = g * u / (1.0f + __expf(-g));
                        hh[jj] = __float2half(h);
                    }
                }
            } else {
#pragma unroll
                for (int i = 0; i < 8; i++) {
                    int m = mbx * BM + ty * 8 + i;
                    float* co = Cout + (size_t)m * ldout + (size_t)nb * 256 + tx * 8;
#pragma unroll
                    for (int jj = 0; jj < 8; jj++) { co[jj] = acc0[i][jj]; co[128 + jj] = acc1[i][jj]; }
                }
            }
        }
        __syncthreads();
    }
#endif
}

// ======================= fp32 -> fp16 convert (x and wgu in one launch) ===========
__global__ void convert2_kernel(const float4* __restrict__ src_a, long n4a,
                                const float4* __restrict__ src_b, long n4b,
                                __half2* __restrict__ dst_a,
                                __half2* __restrict__ dst_b)
{
    long i = (long)blockIdx.x * blockDim.x + threadIdx.x;
    if (i < n4a) {
        float4 v = src_a[i];
        dst_a[2*i]   = __floats2half2_rn(v.x, v.y);
        dst_a[2*i+1] = __floats2half2_rn(v.z, v.w);
    } else if (i < n4a + n4b) {
        long k = i - n4a;
        float4 v = src_b[k];
        dst_b[2*k]   = __floats2half2_rn(v.x, v.y);
        dst_b[2*k+1] = __floats2half2_rn(v.z, v.w);
    }
}

// ======================= host: tensormap building =======================

typedef CUresult (*EncodeTiledFn)(
    CUtensorMap*, CUtensorMapDataType, cuuint32_t, void*,
    const cuuint64_t*, const cuuint64_t*, const cuuint32_t*, const cuuint32_t*,
    CUtensorMapInterleave, CUtensorMapSwizzle, CUtensorMapL2promotion,
    CUtensorMapFloatOOBfill);

static void build_map(EncodeTiledFn enc, CUtensorMap* m, void* base,
                      unsigned long long dim0, unsigned long long dim1)
{
    cuuint64_t dims[3]    = {dim0, dim1, 1};
    cuuint64_t strides[2] = {dim0 * 2ull, dim0 * dim1 * 2ull};
    cuuint32_t box[3]     = {KC, BM, 1};          // 64 fp16 = 128B (SW128 atom), 128 rows
    cuuint32_t es[3]      = {1, 1, 1};
    enc(m, CU_TENSOR_MAP_DATA_TYPE_FLOAT16, 3, base, dims, strides, box, es,
        CU_TENSOR_MAP_INTERLEAVE_NONE, CU_TENSOR_MAP_SWIZZLE_128B,
        CU_TENSOR_MAP_L2_PROMOTION_L2_128B, CU_TENSOR_MAP_FLOAT_OOB_FILL_NONE);
}

// ======================= launch =======================
extern "C" void kernel_launch(void* const* d_in, const int* in_sizes, int n_in,
                              void* d_out, int out_size)
{
    const float* x   = (const float*)d_in[0];
    const float* wgu = (const float*)d_in[1];
    const float* wd  = (const float*)d_in[2];
    float* out       = (float*)d_out;

    fp16 *xc, *wguc, *wdc, *hc;
    cudaGetSymbolAddress((void**)&xc,  g_x);
    cudaGetSymbolAddress((void**)&wguc, g_wgu);
    cudaGetSymbolAddress((void**)&wdc, g_wd);
    cudaGetSymbolAddress((void**)&hc,  g_h);

    // driver entry point for tensormap encoding (avoids -lcuda link dependency)
    void* fn = nullptr;
    cudaDriverEntryPointQueryResult qr;
    cudaGetDriverEntryPoint("cuTensorMapEncodeTiled", &fn, cudaEnableDefault, &qr);
    EncodeTiledFn enc = (EncodeTiledFn)fn;

    CUtensorMap map_x, map_wgu, map_h, map_wd;
    build_map(enc, &map_x,   xc,   H_DIM, M_DIM);          // [4096, 4096]
    build_map(enc, &map_wgu, wguc, H_DIM, 2ull * I_DIM);   // [4096, 22016]
    build_map(enc, &map_h,   hc,   I_DIM, M_DIM);          // [11008, 4096]
    build_map(enc, &map_wd,  wdc,  I_DIM, H_DIM);          // [11008, 4096]

    cudaFuncSetAttribute(mlp_gemm<0>, cudaFuncAttributeMaxDynamicSharedMemorySize, SMEM_TOTAL);
    cudaFuncSetAttribute(mlp_gemm<1>, cudaFuncAttributeMaxDynamicSharedMemorySize, SMEM_TOTAL);

    // convert x + wgu to fp16 in ONE launch (needed by GEMM1). wd is converted
    // INSIDE GEMM1 by its spare warps (overlapped with the mainloop).
    const long n4x = (long)M_DIM * H_DIM / 4;
    const long n4w = (long)2 * I_DIM * H_DIM / 4;
    convert2_kernel<<<(unsigned)((n4x + n4w + 255) / 256), 256>>>(
        (const float4*)x, n4x, (const float4*)wgu, n4w,
        (__half2*)xc, (__half2*)wguc);

    const long wd_n4 = (long)H_DIM * I_DIM / 4;

    // GEMM1 (fused SwiGLU -> h fp16, + wd convert on spare warps)
    mlp_gemm<1><<<dim3(2 * NCLUSTERS, 1, 1), NTHREADS, SMEM_TOTAL>>>(
        map_x, map_wgu,
        xc, wguc, wguc + (size_t)I_DIM * H_DIM,
        H_DIM, I_DIM,
        nullptr, hc,
        (const float4*)wd, (__half2*)wdc, wd_n4);

    // GEMM2: out = h @ Wd^T
    mlp_gemm<0><<<dim3(2 * NCLUSTERS, 1, 1), NTHREADS, SMEM_TOTAL>>>(
        map_h, map_wd,
        hc, wdc, nullptr,
        I_DIM, H_DIM,
        out, nullptr,
        nullptr, nullptr, 0);
}